// round 14
// baseline (speedup 1.0000x reference)
#include <cuda_runtime.h>
#include <cuda_fp16.h>
#include <cstdint>
#include <math.h>

#define BDIM 4096
#define INDIM 1024
#define HDIM 2048
#define OUTDIM 1024
#define EDIM 16
#define MAX_TILES 48

#define GRID_PRE 304
#define GRID_EXP 304
#define GRID_POST 256

// ---------------- scratch (__device__ globals; no allocation allowed) ----------------
__device__ __half g_obs[BDIM * INDIM];
__device__ __half g_y[BDIM * HDIM];
__device__ __half g_z[BDIM * HDIM];
__device__ __half g_wpre[HDIM * INDIM];
__device__ __half g_wexp[EDIM * HDIM * HDIM];
__device__ __half g_wpost[OUTDIM * HDIM];
__device__ int g_perm[BDIM];
__device__ int g_tile_expert[MAX_TILES];
__device__ int g_tile_row0[MAX_TILES];
__device__ int g_tile_nrows[MAX_TILES];
__device__ int g_ctr[4];

// ---------------- counters (re-init every replay) ----------------
__global__ void k_zctr() {
    g_ctr[0] = GRID_PRE;
    g_ctr[1] = GRID_EXP;
    g_ctr[2] = GRID_POST;
}

// ---------------- fused routing ----------------
__global__ __launch_bounds__(512) void k_route(const int* __restrict__ idx) {
    __shared__ int cnt[EDIM];
    __shared__ int cur[EDIM];
    int tid = threadIdx.x;
    if (tid < EDIM) cnt[tid] = 0;
    __syncthreads();
#pragma unroll
    for (int i = 0; i < BDIM / 512; i++)
        atomicAdd(&cnt[idx[tid + i * 512]], 1);
    __syncthreads();
    if (tid == 0) {
        int off = 0, t = 0;
        for (int e = 0; e < EDIM; e++) {
            int n = cnt[e];
            cur[e] = off;
            int nt = (n + 127) >> 7;
            for (int i = 0; i < nt; i++) {
                g_tile_expert[t] = e;
                g_tile_row0[t] = off + (i << 7);
                int rem = n - (i << 7);
                g_tile_nrows[t] = rem < 128 ? rem : 128;
                t++;
            }
            off += n;
        }
        for (; t < MAX_TILES; t++) g_tile_expert[t] = -1;
    }
    __syncthreads();
#pragma unroll
    for (int i = 0; i < BDIM / 512; i++) {
        int b = tid + i * 512;
        int p = atomicAdd(&cur[idx[b]], 1);
        g_perm[p] = b;
    }
}

// ---------------- fp32 -> fp16 cast (grid-stride) ----------------
__global__ __launch_bounds__(256) void k_tohalf(const float* __restrict__ in,
                                                __half* __restrict__ h, int n4) {
    int stride = gridDim.x * blockDim.x;
    for (int i = blockIdx.x * blockDim.x + threadIdx.x; i < n4; i += stride) {
        float4 v = ((const float4*)in)[i];
        ((__half2*)h)[i * 2 + 0] = __floats2half2_rn(v.x, v.y);
        ((__half2*)h)[i * 2 + 1] = __floats2half2_rn(v.z, v.w);
    }
}

// ---------------- PTX helpers ----------------
__device__ __forceinline__ uint32_t smem_to_u32(const void* p) {
    uint32_t a;
    asm("{ .reg .u64 t; cvta.to.shared.u64 t, %1; cvt.u32.u64 %0, t; }" : "=r"(a) : "l"(p));
    return a;
}
#define CP16(dst, src) \
    asm volatile("cp.async.cg.shared.global [%0], [%1], 16;" :: "r"(dst), "l"(src))
#define CP_COMMIT() asm volatile("cp.async.commit_group;" ::: "memory")
#define CP_WAIT1() asm volatile("cp.async.wait_group 1;" ::: "memory")
#define LDSM4(r, addr) \
    asm volatile("ldmatrix.sync.aligned.m8n8.x4.shared.b16 {%0,%1,%2,%3}, [%4];" \
        : "=r"((r)[0]), "=r"((r)[1]), "=r"((r)[2]), "=r"((r)[3]) : "r"(addr))
#define MMA(c, a, b0, b1) \
    asm volatile("mma.sync.aligned.m16n8k16.row.col.f32.f16.f16.f32 " \
        "{%0,%1,%2,%3}, {%4,%5,%6,%7}, {%8,%9}, {%0,%1,%2,%3};" \
        : "+f"((c)[0]), "+f"((c)[1]), "+f"((c)[2]), "+f"((c)[3]) \
        : "r"((a)[0]), "r"((a)[1]), "r"((a)[2]), "r"((a)[3]), "r"(b0), "r"(b1))
#define SWZ(off) ((off) ^ (((off) >> 3) & 0x70))

// ---------------- GEMM config: 2 CTAs/SM, persistent ----------------
#define BM 128
#define BN 128
#define BK 64
#define STAGES 3
#define A_TILE_B 16384
#define B_TILE_B 16384
#define STAGE_B (A_TILE_B + B_TILE_B)       // 32KB
#define SM_STAGE0 1024
#define SMEM_TOTAL (SM_STAGE0 + STAGES * STAGE_B)   // 99328

// Persistent tiled GEMM: C = tanh(A @ W^T + bias); fp16 single-pass.
// Tiles popped from global counter after static first tile.
template <bool GATHER, bool OUT_HALF>
__global__ __launch_bounds__(256, 2) void gemm_mma(
    const __half* __restrict__ A0, const __half* __restrict__ W0,
    const float* __restrict__ bias0,
    float* __restrict__ Cf, __half* __restrict__ Ch,
    int K, int ldc, int NB, int nTiles, int* __restrict__ ctr) {
    extern __shared__ char smem[];
    __shared__ int s_tile;
    int tid = threadIdx.x, lane = tid & 31, wid = tid >> 5;
    int* permS = (int*)smem;
    uint32_t sb = smem_to_u32(smem);

    int wm = wid & 1;    // 64-row half
    int wn = wid >> 1;   // 32-col group
    int arow = (lane & 7) + ((lane >> 3) & 1) * 8;
    int brow = (lane & 7) + ((lane >> 4) & 1) * 8;
    int NC = K / BK;

    int t = blockIdx.x;
    while (t < nTiles) {
        int mtile = t / NB;
        int n0 = (t - mtile * NB) * BN;
        int nrows = BM;
        const __half* Ah = A0;
        const __half* Wh = W0;
        const float* bias = bias0;
        bool live = true;
        if (GATHER) {
            int e = g_tile_expert[mtile];
            if (e < 0) {
                live = false;
            } else {
                nrows = g_tile_nrows[mtile];
                int row0 = g_tile_row0[mtile];
                Wh = W0 + (size_t)e * HDIM * HDIM;
                bias = bias0 + (size_t)e * HDIM;
                if (tid < BM) {
                    int rr = tid < nrows ? tid : nrows - 1;
                    permS[tid] = g_perm[row0 + rr];
                }
            }
        } else {
            Ah = A0 + (size_t)mtile * BM * K;
        }

        if (live) {
            __syncthreads();    // permS visible (and prev tile fully done)

            uint32_t swa[4];
            const __half *ah_src[4], *bh_src[4];
#pragma unroll
            for (int i = 0; i < 4; i++) {
                int idx = tid + i * 256;
                int r = idx >> 3;
                int cb = (idx & 7) * 16;
                swa[i] = SWZ(r * 128 + cb);
                int ce = cb >> 1;
                int ar = GATHER ? permS[r] : r;
                ah_src[i] = Ah + (size_t)ar * K + ce;
                bh_src[i] = Wh + (size_t)(n0 + r) * K + ce;
            }
            auto issue = [&](int stage, int kc) {
                uint32_t base = sb + SM_STAGE0 + stage * STAGE_B;
#pragma unroll
                for (int i = 0; i < 4; i++) {
                    CP16(base + swa[i], ah_src[i] + kc);
                    CP16(base + A_TILE_B + swa[i], bh_src[i] + kc);
                }
            };

            issue(0, 0); CP_COMMIT();
            issue(1, BK); CP_COMMIT();

            float acc[4][4][4];
#pragma unroll
            for (int m = 0; m < 4; m++)
#pragma unroll
                for (int n = 0; n < 4; n++)
#pragma unroll
                    for (int q = 0; q < 4; q++) acc[m][n][q] = 0.f;

            for (int c = 0; c < NC; c++) {
                CP_WAIT1();
                __syncthreads();
                if (c + 2 < NC) issue((c + 2) % STAGES, (c + 2) * BK);
                CP_COMMIT();
                uint32_t base = sb + SM_STAGE0 + (c % STAGES) * STAGE_B;
#pragma unroll
                for (int kk = 0; kk < 4; kk++) {
                    int k0 = kk * 16;
                    int acol = k0 + (lane >> 4) * 8;
                    int bcol = k0 + ((lane >> 3) & 1) * 8;
                    uint32_t ah[4][4];
#pragma unroll
                    for (int m = 0; m < 4; m++) {
                        uint32_t off = SWZ((wm * 64 + m * 16 + arow) * 128 + acol * 2);
                        LDSM4(ah[m], base + off);
                    }
                    uint32_t bh[2][4];
#pragma unroll
                    for (int p = 0; p < 2; p++) {
                        uint32_t off = SWZ((wn * 32 + p * 16 + brow) * 128 + bcol * 2);
                        LDSM4(bh[p], base + A_TILE_B + off);
                    }
#pragma unroll
                    for (int m = 0; m < 4; m++)
#pragma unroll
                        for (int n = 0; n < 4; n++) {
                            uint32_t b0 = bh[n >> 1][(n & 1) * 2];
                            uint32_t b1 = bh[n >> 1][(n & 1) * 2 + 1];
                            MMA(acc[m][n], ah[m], b0, b1);
                        }
                }
            }

            int g = lane >> 2, t4 = lane & 3;
#pragma unroll
            for (int m = 0; m < 4; m++) {
#pragma unroll
                for (int half_ = 0; half_ < 2; half_++) {
                    int rl = wm * 64 + m * 16 + g + half_ * 8;
                    if (GATHER && rl >= nrows) continue;
                    int grow = GATHER ? permS[rl] : mtile * BM + rl;
#pragma unroll
                    for (int n = 0; n < 4; n++) {
                        int col = n0 + wn * 32 + n * 8 + t4 * 2;
                        float v0 = tanhf(acc[m][n][half_ * 2 + 0] + bias[col]);
                        float v1 = tanhf(acc[m][n][half_ * 2 + 1] + bias[col + 1]);
                        if (OUT_HALF) {
                            *(__half2*)(Ch + (size_t)grow * ldc + col) =
                                __floats2half2_rn(v0, v1);
                        } else {
                            *(float2*)(Cf + (size_t)grow * ldc + col) =
                                make_float2(v0, v1);
                        }
                    }
                }
            }
        }

        // steal next tile
        if (tid == 0) s_tile = atomicAdd(ctr, 1);
        __syncthreads();
        t = s_tile;
    }
}

// ---------------- launch ----------------
extern "C" void kernel_launch(void* const* d_in, const int* in_sizes, int n_in,
                              void* d_out, int out_size) {
    const float* obs   = (const float*)d_in[0];
    const int*   swidx = (const int*)d_in[1];
    const float* pre_w = (const float*)d_in[2];
    const float* pre_b = (const float*)d_in[3];
    const float* ew    = (const float*)d_in[4];
    const float* eb    = (const float*)d_in[5];
    const float* pw    = (const float*)d_in[6];
    const float* pb    = (const float*)d_in[7];
    float* out = (float*)d_out;

    __half *obs_h, *y_h, *z_h, *wpre, *wexp, *wpost;
    int* ctr;
    cudaGetSymbolAddress((void**)&obs_h, g_obs);
    cudaGetSymbolAddress((void**)&y_h, g_y);
    cudaGetSymbolAddress((void**)&z_h, g_z);
    cudaGetSymbolAddress((void**)&wpre, g_wpre);
    cudaGetSymbolAddress((void**)&wexp, g_wexp);
    cudaGetSymbolAddress((void**)&wpost, g_wpost);
    cudaGetSymbolAddress((void**)&ctr, g_ctr);

    static cudaStream_t sR = nullptr, sC = nullptr;
    static cudaEvent_t evFork, evRoute, evWpre, evWexp, evWpost;
    if (!sR) {
        cudaStreamCreateWithFlags(&sR, cudaStreamNonBlocking);
        cudaStreamCreateWithFlags(&sC, cudaStreamNonBlocking);
        cudaEventCreateWithFlags(&evFork, cudaEventDisableTiming);
        cudaEventCreateWithFlags(&evRoute, cudaEventDisableTiming);
        cudaEventCreateWithFlags(&evWpre, cudaEventDisableTiming);
        cudaEventCreateWithFlags(&evWexp, cudaEventDisableTiming);
        cudaEventCreateWithFlags(&evWpost, cudaEventDisableTiming);
        cudaFuncSetAttribute(gemm_mma<false, true>,
                             cudaFuncAttributeMaxDynamicSharedMemorySize, SMEM_TOTAL);
        cudaFuncSetAttribute(gemm_mma<true, true>,
                             cudaFuncAttributeMaxDynamicSharedMemorySize, SMEM_TOTAL);
        cudaFuncSetAttribute(gemm_mma<false, false>,
                             cudaFuncAttributeMaxDynamicSharedMemorySize, SMEM_TOTAL);
    }

    const int CONV_GRID = 1184;

    // counters first (pre/expert/post all pop after this on the main stream)
    k_zctr<<<1, 1>>>();

    // fork side streams
    cudaEventRecord(evFork, 0);
    cudaStreamWaitEvent(sR, evFork, 0);
    cudaStreamWaitEvent(sC, evFork, 0);

    // routing on sR
    k_route<<<1, 512, 0, sR>>>(swidx);
    cudaEventRecord(evRoute, sR);

    // weight converts on sC: wpre, wexp, wpost
    {
        int n4 = HDIM * INDIM / 4;
        k_tohalf<<<(n4 + 255) / 256 < CONV_GRID ? (n4 + 255) / 256 : CONV_GRID,
                   256, 0, sC>>>(pre_w, wpre, n4);
        cudaEventRecord(evWpre, sC);
        n4 = EDIM * HDIM * HDIM / 4;
        k_tohalf<<<CONV_GRID, 256, 0, sC>>>(ew, wexp, n4);
        cudaEventRecord(evWexp, sC);
        n4 = OUTDIM * HDIM / 4;
        k_tohalf<<<(n4 + 255) / 256 < CONV_GRID ? (n4 + 255) / 256 : CONV_GRID,
                   256, 0, sC>>>(pw, wpost, n4);
        cudaEventRecord(evWpost, sC);
    }

    // critical path: obs convert (parallel with wpre)
    {
        int n4 = BDIM * INDIM / 4;
        k_tohalf<<<(n4 + 255) / 256 < CONV_GRID ? (n4 + 255) / 256 : CONV_GRID,
                   256>>>(obs, obs_h, n4);
    }

    // pre: y = tanh(obs @ pre_w^T + pre_b): tiles 16 x 32 = 512
    cudaStreamWaitEvent(0, evWpre, 0);
    gemm_mma<false, true><<<GRID_PRE, 256, SMEM_TOTAL>>>(
        obs_h, wpre, pre_b, nullptr, y_h, INDIM, HDIM,
        HDIM / BN, (HDIM / BN) * (BDIM / BM), ctr + 0);

    // experts: z = tanh(W_e @ y + b_e): tiles 16 x 48 = 768 (empties skipped)
    cudaStreamWaitEvent(0, evRoute, 0);
    cudaStreamWaitEvent(0, evWexp, 0);
    gemm_mma<true, true><<<GRID_EXP, 256, SMEM_TOTAL>>>(
        y_h, wexp, eb, nullptr, z_h, HDIM, HDIM,
        HDIM / BN, (HDIM / BN) * MAX_TILES, ctr + 1);

    // post: out = tanh(z @ post_w^T + post_b): tiles 8 x 32 = 256
    cudaStreamWaitEvent(0, evWpost, 0);
    gemm_mma<false, false><<<GRID_POST, 256, SMEM_TOTAL>>>(
        z_h, wpost, pb, out, nullptr, HDIM, OUTDIM,
        OUTDIM / BN, (OUTDIM / BN) * (BDIM / BM), ctr + 2);
}

// round 15
// speedup vs baseline: 1.2290x; 1.2290x over previous
#include <cuda_runtime.h>
#include <cuda_fp16.h>
#include <cstdint>
#include <math.h>

#define BDIM 4096
#define INDIM 1024
#define HDIM 2048
#define OUTDIM 1024
#define EDIM 16
#define MAX_TILES 48

// ---------------- scratch (__device__ globals; no allocation allowed) ----------------
__device__ __half g_obs[BDIM * INDIM];
__device__ __half g_y[BDIM * HDIM];
__device__ __half g_z[BDIM * HDIM];
__device__ __half g_wpre[HDIM * INDIM];
__device__ __half g_wexp[EDIM * HDIM * HDIM];
__device__ __half g_wpost[OUTDIM * HDIM];
__device__ int g_perm[BDIM];
__device__ int g_tile_expert[MAX_TILES];
__device__ int g_tile_row0[MAX_TILES];
__device__ int g_tile_nrows[MAX_TILES];

// ---------------- fused routing ----------------
__global__ __launch_bounds__(512) void k_route(const int* __restrict__ idx) {
    __shared__ int cnt[EDIM];
    __shared__ int cur[EDIM];
    int tid = threadIdx.x;
    if (tid < EDIM) cnt[tid] = 0;
    __syncthreads();
#pragma unroll
    for (int i = 0; i < BDIM / 512; i++)
        atomicAdd(&cnt[idx[tid + i * 512]], 1);
    __syncthreads();
    if (tid == 0) {
        int off = 0, t = 0;
        for (int e = 0; e < EDIM; e++) {
            int n = cnt[e];
            cur[e] = off;
            int nt = (n + 127) >> 7;
            for (int i = 0; i < nt; i++) {
                g_tile_expert[t] = e;
                g_tile_row0[t] = off + (i << 7);
                int rem = n - (i << 7);
                g_tile_nrows[t] = rem < 128 ? rem : 128;
                t++;
            }
            off += n;
        }
        for (; t < MAX_TILES; t++) g_tile_expert[t] = -1;
    }
    __syncthreads();
#pragma unroll
    for (int i = 0; i < BDIM / 512; i++) {
        int b = tid + i * 512;
        int p = atomicAdd(&cur[idx[b]], 1);
        g_perm[p] = b;
    }
}

// ---------------- fp32 -> fp16 cast (grid-stride) ----------------
__global__ __launch_bounds__(256) void k_tohalf(const float* __restrict__ in,
                                                __half* __restrict__ h, int n4) {
    int stride = gridDim.x * blockDim.x;
    for (int i = blockIdx.x * blockDim.x + threadIdx.x; i < n4; i += stride) {
        float4 v = ((const float4*)in)[i];
        ((__half2*)h)[i * 2 + 0] = __floats2half2_rn(v.x, v.y);
        ((__half2*)h)[i * 2 + 1] = __floats2half2_rn(v.z, v.w);
    }
}

// ---------------- PTX helpers ----------------
__device__ __forceinline__ uint32_t smem_to_u32(const void* p) {
    uint32_t a;
    asm("{ .reg .u64 t; cvta.to.shared.u64 t, %1; cvt.u32.u64 %0, t; }" : "=r"(a) : "l"(p));
    return a;
}
#define CP16(dst, src) \
    asm volatile("cp.async.cg.shared.global [%0], [%1], 16;" :: "r"(dst), "l"(src))
#define CP_COMMIT() asm volatile("cp.async.commit_group;" ::: "memory")
#define CP_WAIT1() asm volatile("cp.async.wait_group 1;" ::: "memory")
#define LDSM4(r, addr) \
    asm volatile("ldmatrix.sync.aligned.m8n8.x4.shared.b16 {%0,%1,%2,%3}, [%4];" \
        : "=r"((r)[0]), "=r"((r)[1]), "=r"((r)[2]), "=r"((r)[3]) : "r"(addr))
#define MMA(c, a, b0, b1) \
    asm volatile("mma.sync.aligned.m16n8k16.row.col.f32.f16.f16.f32 " \
        "{%0,%1,%2,%3}, {%4,%5,%6,%7}, {%8,%9}, {%0,%1,%2,%3};" \
        : "+f"((c)[0]), "+f"((c)[1]), "+f"((c)[2]), "+f"((c)[3]) \
        : "r"((a)[0]), "r"((a)[1]), "r"((a)[2]), "r"((a)[3]), "r"(b0), "r"(b1))
#define SWZ(off) ((off) ^ (((off) >> 3) & 0x70))

// ---------------- GEMM config: 4 warps, 64x64 warp tiles, 2 CTAs/SM ----------------
#define BM 128
#define BN 128
#define BK 64
#define NTHREADS 128
#define STAGES 3
#define A_TILE_B 16384
#define B_TILE_B 16384
#define STAGE_B (A_TILE_B + B_TILE_B)       // 32KB
#define SM_STAGE0 1024
#define SMEM_TOTAL (SM_STAGE0 + STAGES * STAGE_B)   // 99328 -> 2 CTAs/SM

// C[M,N] = tanh(A @ W^T + bias); single-pass fp16, fp32 accumulate.
// 4 warps as 2(M) x 2(N); warp tile 64x64; acc 128 regs/thread.
// grid: x = N-block, y = M-tile
template <bool GATHER, bool OUT_HALF>
__global__ __launch_bounds__(NTHREADS, 2) void gemm_mma(
    const __half* __restrict__ Ah, const __half* __restrict__ Wh,
    const float* __restrict__ bias,
    float* __restrict__ Cf, __half* __restrict__ Ch,
    int K, int ldc) {
    extern __shared__ char smem[];
    int tid = threadIdx.x, lane = tid & 31, wid = tid >> 5;
    int* permS = (int*)smem;

    int nrows = BM;
    if (GATHER) {
        int e = g_tile_expert[blockIdx.y];
        if (e < 0) return;
        nrows = g_tile_nrows[blockIdx.y];
        int row0 = g_tile_row0[blockIdx.y];
        Wh += (size_t)e * HDIM * HDIM;
        bias += (size_t)e * HDIM;
        int rr = tid < nrows ? tid : nrows - 1;
        permS[tid] = g_perm[row0 + rr];            // NTHREADS == BM
    } else {
        Ah += (size_t)blockIdx.y * BM * K;
    }
    int n0 = blockIdx.x * BN;
    __syncthreads();

    uint32_t sb = smem_to_u32(smem);

    // cp.async: A and B each 128x64 fp16 = 1024 x 16B; 8 each per thread
    uint32_t swa[8];
    const __half *ah_src[8], *bh_src[8];
#pragma unroll
    for (int i = 0; i < 8; i++) {
        int idx = tid + i * NTHREADS;
        int r = idx >> 3;
        int cb = (idx & 7) * 16;
        swa[i] = SWZ(r * 128 + cb);
        int ce = cb >> 1;
        int ar = GATHER ? permS[r] : r;
        ah_src[i] = Ah + (size_t)ar * K + ce;
        bh_src[i] = Wh + (size_t)(n0 + r) * K + ce;
    }

    auto issue = [&](int stage, int kc) {
        uint32_t base = sb + SM_STAGE0 + stage * STAGE_B;
#pragma unroll
        for (int i = 0; i < 8; i++) {
            CP16(base + swa[i], ah_src[i] + kc);
            CP16(base + A_TILE_B + swa[i], bh_src[i] + kc);
        }
    };

    int NC = K / BK;
    issue(0, 0); CP_COMMIT();
    issue(1, BK); CP_COMMIT();

    float acc[4][8][4];
#pragma unroll
    for (int m = 0; m < 4; m++)
#pragma unroll
        for (int n = 0; n < 8; n++)
#pragma unroll
            for (int q = 0; q < 4; q++) acc[m][n][q] = 0.f;

    int wm = wid & 1;    // 64-row half
    int wn = wid >> 1;   // 64-col half
    int arow = (lane & 7) + ((lane >> 3) & 1) * 8;
    int brow = (lane & 7) + ((lane >> 4) & 1) * 8;

    for (int c = 0; c < NC; c++) {
        CP_WAIT1();
        __syncthreads();                    // single sync per chunk
        if (c + 2 < NC) issue((c + 2) % STAGES, (c + 2) * BK);
        CP_COMMIT();
        uint32_t base = sb + SM_STAGE0 + (c % STAGES) * STAGE_B;
#pragma unroll
        for (int kk = 0; kk < 4; kk++) {
            int k0 = kk * 16;
            int acol = k0 + (lane >> 4) * 8;
            int bcol = k0 + ((lane >> 3) & 1) * 8;
            uint32_t ah[4][4];
#pragma unroll
            for (int m = 0; m < 4; m++) {
                uint32_t off = SWZ((wm * 64 + m * 16 + arow) * 128 + acol * 2);
                LDSM4(ah[m], base + off);
            }
            uint32_t bh[4][4];
#pragma unroll
            for (int p = 0; p < 4; p++) {
                uint32_t off = SWZ((wn * 64 + p * 16 + brow) * 128 + bcol * 2);
                LDSM4(bh[p], base + A_TILE_B + off);
            }
#pragma unroll
            for (int m = 0; m < 4; m++)
#pragma unroll
                for (int n = 0; n < 8; n++) {
                    uint32_t b0 = bh[n >> 1][(n & 1) * 2];
                    uint32_t b1 = bh[n >> 1][(n & 1) * 2 + 1];
                    MMA(acc[m][n], ah[m], b0, b1);
                }
        }
    }

    int g = lane >> 2, t4 = lane & 3;
#pragma unroll
    for (int m = 0; m < 4; m++) {
#pragma unroll
        for (int half_ = 0; half_ < 2; half_++) {
            int rl = wm * 64 + m * 16 + g + half_ * 8;
            if (GATHER && rl >= nrows) continue;
            int grow = GATHER ? permS[rl] : blockIdx.y * BM + rl;
#pragma unroll
            for (int n = 0; n < 8; n++) {
                int col = n0 + wn * 64 + n * 8 + t4 * 2;
                float v0 = tanhf(acc[m][n][half_ * 2 + 0] + bias[col]);
                float v1 = tanhf(acc[m][n][half_ * 2 + 1] + bias[col + 1]);
                if (OUT_HALF) {
                    *(__half2*)(Ch + (size_t)grow * ldc + col) = __floats2half2_rn(v0, v1);
                } else {
                    *(float2*)(Cf + (size_t)grow * ldc + col) = make_float2(v0, v1);
                }
            }
        }
    }
}

// ---------------- launch ----------------
extern "C" void kernel_launch(void* const* d_in, const int* in_sizes, int n_in,
                              void* d_out, int out_size) {
    const float* obs   = (const float*)d_in[0];
    const int*   swidx = (const int*)d_in[1];
    const float* pre_w = (const float*)d_in[2];
    const float* pre_b = (const float*)d_in[3];
    const float* ew    = (const float*)d_in[4];
    const float* eb    = (const float*)d_in[5];
    const float* pw    = (const float*)d_in[6];
    const float* pb    = (const float*)d_in[7];
    float* out = (float*)d_out;

    __half *obs_h, *y_h, *z_h, *wpre, *wexp, *wpost;
    cudaGetSymbolAddress((void**)&obs_h, g_obs);
    cudaGetSymbolAddress((void**)&y_h, g_y);
    cudaGetSymbolAddress((void**)&z_h, g_z);
    cudaGetSymbolAddress((void**)&wpre, g_wpre);
    cudaGetSymbolAddress((void**)&wexp, g_wexp);
    cudaGetSymbolAddress((void**)&wpost, g_wpost);

    static cudaStream_t sR = nullptr, sC = nullptr;
    static cudaEvent_t evFork, evRoute, evWpre, evWexp, evWpost;
    if (!sR) {
        cudaStreamCreateWithFlags(&sR, cudaStreamNonBlocking);
        cudaStreamCreateWithFlags(&sC, cudaStreamNonBlocking);
        cudaEventCreateWithFlags(&evFork, cudaEventDisableTiming);
        cudaEventCreateWithFlags(&evRoute, cudaEventDisableTiming);
        cudaEventCreateWithFlags(&evWpre, cudaEventDisableTiming);
        cudaEventCreateWithFlags(&evWexp, cudaEventDisableTiming);
        cudaEventCreateWithFlags(&evWpost, cudaEventDisableTiming);
        cudaFuncSetAttribute(gemm_mma<false, true>,
                             cudaFuncAttributeMaxDynamicSharedMemorySize, SMEM_TOTAL);
        cudaFuncSetAttribute(gemm_mma<true, true>,
                             cudaFuncAttributeMaxDynamicSharedMemorySize, SMEM_TOTAL);
        cudaFuncSetAttribute(gemm_mma<false, false>,
                             cudaFuncAttributeMaxDynamicSharedMemorySize, SMEM_TOTAL);
    }

    const int CONV_GRID = 1184;

    // fork side streams
    cudaEventRecord(evFork, 0);
    cudaStreamWaitEvent(sR, evFork, 0);
    cudaStreamWaitEvent(sC, evFork, 0);

    // routing on sR
    k_route<<<1, 512, 0, sR>>>(swidx);
    cudaEventRecord(evRoute, sR);

    // weight converts on sC: wpre, wexp, wpost
    {
        int n4 = HDIM * INDIM / 4;
        k_tohalf<<<(n4 + 255) / 256 < CONV_GRID ? (n4 + 255) / 256 : CONV_GRID,
                   256, 0, sC>>>(pre_w, wpre, n4);
        cudaEventRecord(evWpre, sC);
        n4 = EDIM * HDIM * HDIM / 4;
        k_tohalf<<<CONV_GRID, 256, 0, sC>>>(ew, wexp, n4);
        cudaEventRecord(evWexp, sC);
        n4 = OUTDIM * HDIM / 4;
        k_tohalf<<<(n4 + 255) / 256 < CONV_GRID ? (n4 + 255) / 256 : CONV_GRID,
                   256, 0, sC>>>(pw, wpost, n4);
        cudaEventRecord(evWpost, sC);
    }

    // critical path: obs convert (parallel with wpre)
    {
        int n4 = BDIM * INDIM / 4;
        k_tohalf<<<(n4 + 255) / 256 < CONV_GRID ? (n4 + 255) / 256 : CONV_GRID,
                   256>>>(obs, obs_h, n4);
    }

    // pre: y = tanh(obs @ pre_w^T + pre_b): M=4096, N=2048, K=1024
    cudaStreamWaitEvent(0, evWpre, 0);
    gemm_mma<false, true><<<dim3(HDIM / BN, BDIM / BM), NTHREADS, SMEM_TOTAL>>>(
        obs_h, wpre, pre_b, nullptr, y_h, INDIM, HDIM);

    // experts: z = tanh(W_e @ y + b_e): gathered rows, N=2048, K=2048
    cudaStreamWaitEvent(0, evRoute, 0);
    cudaStreamWaitEvent(0, evWexp, 0);
    gemm_mma<true, true><<<dim3(HDIM / BN, MAX_TILES), NTHREADS, SMEM_TOTAL>>>(
        y_h, wexp, eb, nullptr, z_h, HDIM, HDIM);

    // post: out = tanh(z @ post_w^T + post_b): M=4096, N=1024, K=2048
    cudaStreamWaitEvent(0, evWpost, 0);
    gemm_mma<false, false><<<dim3(OUTDIM / BN, BDIM / BM), NTHREADS, SMEM_TOTAL>>>(
        z_h, wpost, pb, out, nullptr, HDIM, OUTDIM);
}